// round 14
// baseline (speedup 1.0000x reference)
#include <cuda_runtime.h>
#include <cuda_bf16.h>
#include <math.h>
#include <stdint.h>

#define H_DIM 1024
#define SB 104448
#define OUT_CH 904
#define NMIX 50
#define NPAD 960            // 904 channels padded to 960 (15 x 64)
#define FULLMASK 0xFFFFFFFFu
#define MARGIN_THR 0.75f    // decision-safe margin (>= 2x worst-case y error)
#define WIN_BASE 20.45f     // exact gumbel-window (spread <= 20.412)
#define WIN_WIDE 21.25f     // widened window for approx candidate capture
#define FLAG_CAP (1 << 20)
typedef unsigned long long ull;

__device__ __forceinline__ float fadd_s(float a, float b) { return __fadd_rn(a, b); }

// ---------------- Threefry2x32 (JAX partitionable) ----------------
struct U2 { unsigned a, b; };
__host__ __device__ constexpr unsigned rotl32(unsigned x, int r) {
  return (x << r) | (x >> (32 - r));
}
__host__ __device__ constexpr U2 threefry2x32(unsigned k0, unsigned k1,
                                              unsigned c0, unsigned c1) {
  unsigned ks[3] = {k0, k1, k0 ^ k1 ^ 0x1BD11BDAu};
  unsigned x0 = c0 + k0, x1 = c1 + k1;
  const int rot[2][4] = {{13, 15, 26, 6}, {17, 29, 16, 24}};
#pragma unroll
  for (int g = 0; g < 5; ++g) {
    const int* r = rot[g & 1];
#pragma unroll
    for (int i = 0; i < 4; ++i) { x0 += x1; x1 = rotl32(x1, r[i]); x1 ^= x0; }
    x0 += ks[(g + 1) % 3];
    x1 += ks[(g + 2) % 3] + (unsigned)(g + 1);
  }
  return U2{x0, x1};
}
constexpr unsigned KCMD0 = threefry2x32(0u, 42u, 0u, 0u).a;
constexpr unsigned KCMD1 = threefry2x32(0u, 42u, 0u, 0u).b;
constexpr unsigned KMIX0 = threefry2x32(0u, 42u, 0u, 1u).a;
constexpr unsigned KMIX1 = threefry2x32(0u, 42u, 0u, 1u).b;
constexpr unsigned KG0   = threefry2x32(0u, 42u, 0u, 2u).a;
constexpr unsigned KG1   = threefry2x32(0u, 42u, 0u, 2u).b;

__device__ __forceinline__ float bits_to_f01(unsigned k0, unsigned k1, unsigned idx) {
  U2 o = threefry2x32(k0, k1, 0u, idx);
  return __uint_as_float((((o.a ^ o.b) >> 9) | 0x3f800000u)) - 1.0f;
}
__device__ __forceinline__ float gumbel_at(unsigned k0, unsigned k1, unsigned idx) {
  float u = fmaxf(bits_to_f01(k0, k1, idx), 1.17549435e-38f);
  return -logf(-logf(u));
}
__device__ __forceinline__ float normal_at(unsigned k0, unsigned k1, unsigned idx) {
  const float lo = __int_as_float(0xBF7FFFFF);  // nextafterf(-1,0)
  float u = fmaxf(__fadd_rn(__fmul_rn(bits_to_f01(k0, k1, idx), 2.0f), lo), lo);
  return __fmul_rn(1.41421356237f, erfinvf(u));
}

// ---------------- Device scratch ----------------
__device__ float g_full[(size_t)SB * NPAD];
__device__ __nv_bfloat16 g_ah[(size_t)SB * H_DIM];
__device__ __nv_bfloat16 g_al[(size_t)SB * H_DIM];
__device__ __nv_bfloat16 g_wh[(size_t)NPAD * H_DIM];
__device__ __nv_bfloat16 g_wl[(size_t)NPAD * H_DIM];
__device__ int g_cnt;
__device__ int g_list[FLAG_CAP];

__global__ void zero_cnt_kernel() { g_cnt = 0; }

// ---------------- Splitters ----------------
__global__ void __launch_bounds__(256) split_a_kernel(const float* __restrict__ A) {
  size_t i = (size_t)blockIdx.x * 256 + threadIdx.x;
  float4 v = reinterpret_cast<const float4*>(A)[i];
  float f[4] = {v.x, v.y, v.z, v.w};
  ull hp = 0, lp = 0;
#pragma unroll
  for (int j = 0; j < 4; ++j) {
    __nv_bfloat16 h = __float2bfloat16(f[j]);
    __nv_bfloat16 l = __float2bfloat16(__fadd_rn(f[j], -__bfloat162float(h)));
    hp |= (ull)__bfloat16_as_ushort(h) << (16 * j);
    lp |= (ull)__bfloat16_as_ushort(l) << (16 * j);
  }
  reinterpret_cast<ull*>(g_ah)[i] = hp;
  reinterpret_cast<ull*>(g_al)[i] = lp;
}

__global__ void __launch_bounds__(256) split_w_kernel(const float* __restrict__ W) {
  size_t i = (size_t)blockIdx.x * 256 + threadIdx.x;
  int n = (int)(i / (H_DIM / 4));
  int k4 = (int)(i % (H_DIM / 4));
  ull hp = 0, lp = 0;
  if (n < OUT_CH) {
    float4 v = reinterpret_cast<const float4*>(W + (size_t)n * H_DIM)[k4];
    float f[4] = {v.x, v.y, v.z, v.w};
#pragma unroll
    for (int j = 0; j < 4; ++j) {
      __nv_bfloat16 h = __float2bfloat16(f[j]);
      __nv_bfloat16 l = __float2bfloat16(__fadd_rn(f[j], -__bfloat162float(h)));
      hp |= (ull)__bfloat16_as_ushort(h) << (16 * j);
      lp |= (ull)__bfloat16_as_ushort(l) << (16 * j);
    }
  }
  reinterpret_cast<ull*>(g_wh)[i] = hp;
  reinterpret_cast<ull*>(g_wl)[i] = lp;
}

// ---------------- HMMA GEMM, cp.async double-buffered ----------------
// D = Ah*Wh + Ah*Wl + Al*Wh (+bias). Block 128x64, 8 warps (4m x 2n).
// Same per-element accumulation order as round 13 (bits identical).
#define MS_STRIDE 72  // 64 + 8 pad; 144B rows -> conflict-free ldmatrix
#define BUF_ELEMS ((128 + 128 + 64 + 64) * MS_STRIDE)  // 27648 bf16 = 55296 B

__device__ __forceinline__ void mma_bf16(float c[4], uint32_t a0, uint32_t a1,
                                         uint32_t a2, uint32_t a3,
                                         uint32_t b0, uint32_t b1) {
  asm volatile(
      "mma.sync.aligned.m16n8k16.row.col.f32.bf16.bf16.f32 "
      "{%0,%1,%2,%3}, {%4,%5,%6,%7}, {%8,%9}, {%0,%1,%2,%3};"
      : "+f"(c[0]), "+f"(c[1]), "+f"(c[2]), "+f"(c[3])
      : "r"(a0), "r"(a1), "r"(a2), "r"(a3), "r"(b0), "r"(b1));
}

#define LDMX4(R0, R1, R2, R3, ADDR)                                            \
  asm volatile("ldmatrix.sync.aligned.m8n8.x4.shared.b16 {%0,%1,%2,%3}, [%4];" \
               : "=r"(R0), "=r"(R1), "=r"(R2), "=r"(R3) : "r"(ADDR))

#define CP16(DST, SRC)                                                         \
  asm volatile("cp.async.cg.shared.global [%0], [%1], 16;"                     \
               :: "r"(DST), "l"(SRC) : "memory")
#define CP_COMMIT() asm volatile("cp.async.commit_group;" ::: "memory")
#define CP_WAIT1() asm volatile("cp.async.wait_group 1;" ::: "memory")
#define CP_WAIT0() asm volatile("cp.async.wait_group 0;" ::: "memory")

__device__ __forceinline__ uint32_t smem_u32(const void* p) {
  uint32_t a;
  asm("{ .reg .u64 t; cvta.to.shared.u64 t, %1; cvt.u32.u64 %0, t; }" : "=r"(a) : "l"(p));
  return a;
}

__global__ void __launch_bounds__(256) gemm_full_kernel(const float* __restrict__ bias) {
  extern __shared__ __nv_bfloat16 sm[];
  const uint32_t base0 = smem_u32(sm);

  const int bn = blockIdx.x * 64;   // 15 (fastest -> A hot in L2)
  const int bm = blockIdx.y * 128;  // 816
  const int tid = (int)threadIdx.x;
  const int wid = tid >> 5, lane = tid & 31;
  const int wm = (wid >> 1) * 32, wn = (wid & 1) * 32;
  const int g = lane >> 2, q = lane & 3;

  const int a_row = wm + (lane & 15);
  const int a_sel = (lane & 16) ? 8 : 0;
  const int b_row = wn + (lane & 7) + ((lane & 16) ? 8 : 0);
  const int b_sel = (lane & 8) ? 8 : 0;

  // tile offsets (bf16 elements) within one buffer
  const uint32_t OFF_AH = 0;
  const uint32_t OFF_AL = 128 * MS_STRIDE;
  const uint32_t OFF_WH = 256 * MS_STRIDE;
  const uint32_t OFF_WL = 320 * MS_STRIDE;

  // per-thread copy slots
  const int ar = tid >> 1, ahh = (tid & 1) * 32;          // A: 128 rows x 64B
  const int wr = (tid & 127) >> 1, whh = (tid & 1) * 32;  // W: 64 rows x 64B
  const bool do_w = tid < 128;

  const __nv_bfloat16* gAh = g_ah + (size_t)(bm + ar) * H_DIM + ahh;
  const __nv_bfloat16* gAl = g_al + (size_t)(bm + ar) * H_DIM + ahh;
  const __nv_bfloat16* gWh = g_wh + (size_t)(bn + wr) * H_DIM + whh;
  const __nv_bfloat16* gWl = g_wl + (size_t)(bn + wr) * H_DIM + whh;
  const uint32_t dAh = base0 + (OFF_AH + ar * MS_STRIDE + ahh) * 2;
  const uint32_t dAl = base0 + (OFF_AL + ar * MS_STRIDE + ahh) * 2;
  const uint32_t dWh = base0 + (OFF_WH + wr * MS_STRIDE + whh) * 2;
  const uint32_t dWl = base0 + (OFF_WL + wr * MS_STRIDE + whh) * 2;

#define ISSUE_CHUNK(K0, BUF)                                                   \
  {                                                                            \
    uint32_t bofs = (BUF) * (BUF_ELEMS * 2);                                   \
    _Pragma("unroll") for (int i = 0; i < 4; ++i) {                            \
      CP16(dAh + bofs + i * 16, gAh + (K0) + i * 8);                           \
      CP16(dAl + bofs + i * 16, gAl + (K0) + i * 8);                           \
    }                                                                          \
    if (do_w) {                                                                \
      _Pragma("unroll") for (int i = 0; i < 4; ++i) {                          \
        CP16(dWh + bofs + i * 16, gWh + (K0) + i * 8);                         \
        CP16(dWl + bofs + i * 16, gWl + (K0) + i * 8);                         \
      }                                                                        \
    }                                                                          \
    CP_COMMIT();                                                               \
  }

  float c[2][4][4];
#pragma unroll
  for (int mt = 0; mt < 2; ++mt)
#pragma unroll
    for (int nt = 0; nt < 4; ++nt)
#pragma unroll
      for (int r = 0; r < 4; ++r) c[mt][nt][r] = 0.0f;

  ISSUE_CHUNK(0, 0)

  for (int ch = 0; ch < H_DIM / 64; ++ch) {
    if (ch + 1 < H_DIM / 64) {
      ISSUE_CHUNK((ch + 1) * 64, (ch + 1) & 1)
      CP_WAIT1();
    } else {
      CP_WAIT0();
    }
    __syncthreads();

    const uint32_t bofs = (uint32_t)(ch & 1) * (BUF_ELEMS * 2);
    const uint32_t uAh = base0 + bofs + OFF_AH * 2;
    const uint32_t uAl = base0 + bofs + OFF_AL * 2;
    const uint32_t uWh = base0 + bofs + OFF_WH * 2;
    const uint32_t uWl = base0 + bofs + OFF_WL * 2;

#pragma unroll
    for (int ks = 0; ks < 4; ++ks) {
      const int ak = ks * 16 + a_sel;
      const int bk = ks * 16 + b_sel;
      uint32_t ah[2][4], al[2][4], bh[4][2], bl[4][2];

      uint32_t aoff0 = (uint32_t)(a_row * MS_STRIDE + ak) * 2;
      uint32_t aoff1 = aoff0 + 16 * MS_STRIDE * 2;
      LDMX4(ah[0][0], ah[0][1], ah[0][2], ah[0][3], uAh + aoff0);
      LDMX4(ah[1][0], ah[1][1], ah[1][2], ah[1][3], uAh + aoff1);
      LDMX4(al[0][0], al[0][1], al[0][2], al[0][3], uAl + aoff0);
      LDMX4(al[1][0], al[1][1], al[1][2], al[1][3], uAl + aoff1);

      uint32_t boff0 = (uint32_t)(b_row * MS_STRIDE + bk) * 2;
      uint32_t boff1 = boff0 + 16 * MS_STRIDE * 2;
      LDMX4(bh[0][0], bh[0][1], bh[1][0], bh[1][1], uWh + boff0);
      LDMX4(bh[2][0], bh[2][1], bh[3][0], bh[3][1], uWh + boff1);
      LDMX4(bl[0][0], bl[0][1], bl[1][0], bl[1][1], uWl + boff0);
      LDMX4(bl[2][0], bl[2][1], bl[3][0], bl[3][1], uWl + boff1);

#pragma unroll
      for (int mt = 0; mt < 2; ++mt)
#pragma unroll
        for (int nt = 0; nt < 4; ++nt) {
          mma_bf16(c[mt][nt], ah[mt][0], ah[mt][1], ah[mt][2], ah[mt][3],
                   bh[nt][0], bh[nt][1]);
          mma_bf16(c[mt][nt], ah[mt][0], ah[mt][1], ah[mt][2], ah[mt][3],
                   bl[nt][0], bl[nt][1]);
          mma_bf16(c[mt][nt], al[mt][0], al[mt][1], al[mt][2], al[mt][3],
                   bh[nt][0], bh[nt][1]);
        }
    }
    __syncthreads();
  }

  // epilogue: +bias, store (skip padded cols >= 904)
#pragma unroll
  for (int mt = 0; mt < 2; ++mt) {
#pragma unroll
    for (int nt = 0; nt < 4; ++nt) {
      int row = bm + wm + mt * 16 + g;
      int col = bn + wn + nt * 8 + q * 2;
      if (col < OUT_CH) {
        float b0 = __ldg(&bias[col]), b1 = __ldg(&bias[col + 1]);
        float2* p0 = reinterpret_cast<float2*>(g_full + (size_t)row * NPAD + col);
        float2* p1 = reinterpret_cast<float2*>(g_full + (size_t)(row + 8) * NPAD + col);
        *p0 = make_float2(fadd_s(c[mt][nt][0], b0), fadd_s(c[mt][nt][1], b1));
        *p1 = make_float2(fadd_s(c[mt][nt][2], b0), fadd_s(c[mt][nt][3], b1));
      }
    }
  }
#undef ISSUE_CHUNK
}

// ---------------- Sampling with safe-margin flagging ----------------
__global__ void __launch_bounds__(256) sample_kernel(float* __restrict__ out) {
  int gw = (int)((blockIdx.x * blockDim.x + threadIdx.x) >> 5);
  int lane = (int)(threadIdx.x & 31);
  if (gw >= SB) return;
  const float* row = g_full + (size_t)gw * NPAD;

  // ---- command: top-2 of (x/tau + gumbel) ----
  float m1 = __int_as_float(0xFF800000), m2 = m1;
  int i1 = lane;
  if (lane < 4)
    m1 = __fadd_rn(__fdiv_rn(row[lane], 1e-4f),
                   gumbel_at(KCMD0, KCMD1, (unsigned)(gw * 4 + lane)));
#pragma unroll
  for (int off = 16; off > 0; off >>= 1) {
    float om1 = __shfl_xor_sync(FULLMASK, m1, off);
    int oi1 = __shfl_xor_sync(FULLMASK, i1, off);
    float om2 = __shfl_xor_sync(FULLMASK, m2, off);
    if (om1 > m1 || (om1 == m1 && oi1 < i1)) {
      m2 = fmaxf(m1, om2); m1 = om1; i1 = oi1;
    } else {
      m2 = fmaxf(m2, om1);
    }
  }
  if (lane < 4) out[(size_t)gw * 10 + lane] = (lane == i1) ? 1.0f : 0.0f;
  if (lane == 0 && (m1 - m2) < MARGIN_THR) {
    int pos = atomicAdd(&g_cnt, 1);
    if (pos < FLAG_CAP) g_list[pos] = gw * 8 + 7;
  }

  // ---- 6 mixture rows ----
  for (int j = 0; j < 6; ++j) {
    const float* p = row + 4 + j * 150;
    const int t1 = lane + 32;
    const bool has1 = (t1 < NMIX);
    float x0 = p[lane];
    float x1 = has1 ? p[t1] : __int_as_float(0xFF800000);

    float mx = fmaxf(x0, x1);
#pragma unroll
    for (int off = 16; off > 0; off >>= 1)
      mx = fmaxf(mx, __shfl_xor_sync(FULLMASK, mx, off));
    float s = expf(x0 - mx) + (has1 ? expf(x1 - mx) : 0.0f);
#pragma unroll
    for (int off = 16; off > 0; off >>= 1)
      s += __shfl_xor_sync(FULLMASK, s, off);
    float lse = logf(s) + mx;

    float y0 = __fdiv_rn(__fadd_rn(x0, -lse), 1e-4f);
    float y1 = has1 ? __fdiv_rn(__fadd_rn(x1, -lse), 1e-4f) : __int_as_float(0xFF800000);
    float ym = fmaxf(y0, y1);
#pragma unroll
    for (int off = 16; off > 0; off >>= 1)
      ym = fmaxf(ym, __shfl_xor_sync(FULLMASK, ym, off));

    float thr = ym - WIN_WIDE;
    bool c0 = y0 >= thr;
    bool c1 = has1 && (y1 >= thr);
    unsigned b0m = __ballot_sync(FULLMASK, c0);
    unsigned b1m = __ballot_sync(FULLMASK, c1);
    int mixidx;
    if (__popc(b0m) + __popc(b1m) == 1) {
      mixidx = b0m ? (__ffs(b0m) - 1) : (__ffs(b1m) + 31);
    } else {
      unsigned base = (unsigned)(gw * 6 + j) * 50u;
      float z0 = c0 ? __fadd_rn(y0, gumbel_at(KMIX0, KMIX1, base + (unsigned)lane))
                    : __int_as_float(0xFF800000);
      float z1 = c1 ? __fadd_rn(y1, gumbel_at(KMIX0, KMIX1, base + (unsigned)t1))
                    : __int_as_float(0xFF800000);
      float w1 = z0, w2 = z1;
      int wi = lane;
      if (z1 > z0) { w1 = z1; wi = t1; w2 = z0; }
#pragma unroll
      for (int off = 16; off > 0; off >>= 1) {
        float ow1 = __shfl_xor_sync(FULLMASK, w1, off);
        int owi = __shfl_xor_sync(FULLMASK, wi, off);
        float ow2 = __shfl_xor_sync(FULLMASK, w2, off);
        if (ow1 > w1 || (ow1 == w1 && owi < wi)) {
          w2 = fmaxf(w1, ow2); w1 = ow1; wi = owi;
        } else {
          w2 = fmaxf(w2, ow1);
        }
      }
      mixidx = wi;
      if (lane == 0 && (w1 - w2) < MARGIN_THR) {
        int pos = atomicAdd(&g_cnt, 1);
        if (pos < FLAG_CAP) g_list[pos] = gw * 8 + j;
      }
    }

    if (lane == 0) {
      float mean = p[50 + mixidx];
      float lstd = p[100 + mixidx];
      float nrm = normal_at(KG0, KG1, (unsigned)(gw * 6 + j));
      float noise = __fmul_rn(nrm, 0.01f);
      out[(size_t)gw * 10 + 4 + j] = __fadd_rn(mean, __fmul_rn(expf(lstd), noise));
    }
  }
}

// ---------------- Fixup: exact kc=320 recompute for flagged rows -------------
__global__ void __launch_bounds__(64) fixup_kernel(
    const float* __restrict__ A, const float* __restrict__ W,
    const float* __restrict__ bias, float* __restrict__ out) {
  __shared__ float a_sm[H_DIM];
  __shared__ float x_sm[64];
  __shared__ float z_sm[64];

  int cnt = g_cnt;
  if (cnt > FLAG_CAP) cnt = FLAG_CAP;
  const int tid = (int)threadIdx.x;

  for (int it = (int)blockIdx.x; it < cnt; it += (int)gridDim.x) {
    int code = g_list[it];
    int gw = code >> 3, j = code & 7;

    for (int k = tid; k < H_DIM; k += 64) a_sm[k] = A[(size_t)gw * H_DIM + k];
    __syncthreads();

    int nch = (j == 7) ? 4 : NMIX;
    int ch0 = (j == 7) ? 0 : 4 + 150 * j;

    float x = __int_as_float(0xFF800000);
    if (tid < nch) {
      const float* wr = W + (size_t)(ch0 + tid) * H_DIM;
      float acc = 0.0f, tot = 0.0f;
      int k = 0;
#pragma unroll 1
      for (int seg = 0; seg < 4; ++seg) {
        int ke = (seg < 3) ? (seg + 1) * 320 : H_DIM;
#pragma unroll 4
        for (; k < ke; ++k) acc = fmaf(a_sm[k], __ldg(&wr[k]), acc);
        tot = __fadd_rn(tot, acc);
        acc = 0.0f;
      }
      x = __fadd_rn(tot, __ldg(&bias[ch0 + tid]));
    }
    x_sm[tid] = x;
    __syncthreads();

    if (j == 7) {
      if (tid == 0) {
        float best = __int_as_float(0xFF800000);
        int bi = 0;
        for (int c = 0; c < 4; ++c) {
          float v = __fadd_rn(__fdiv_rn(x_sm[c], 1e-4f),
                              gumbel_at(KCMD0, KCMD1, (unsigned)(gw * 4 + c)));
          if (v > best) { best = v; bi = c; }
        }
        for (int c = 0; c < 4; ++c)
          out[(size_t)gw * 10 + c] = (c == bi) ? 1.0f : 0.0f;
      }
    } else {
      if (tid == 0) {
        float mx = x_sm[0];
        for (int c = 1; c < NMIX; ++c) mx = fmaxf(mx, x_sm[c]);
        float s = 0.0f;
        for (int c = 0; c < NMIX; ++c) s = __fadd_rn(s, expf(x_sm[c] - mx));
        z_sm[0] = logf(s) + mx;
      }
      __syncthreads();
      float lse = z_sm[0];
      __syncthreads();
      float y = (tid < NMIX) ? __fdiv_rn(__fadd_rn(x_sm[tid], -lse), 1e-4f)
                             : __int_as_float(0xFF800000);
      x_sm[tid] = y;
      __syncthreads();
      if (tid == 0) {
        float ym = x_sm[0];
        for (int c = 1; c < NMIX; ++c) ym = fmaxf(ym, x_sm[c]);
        z_sm[1] = ym;
      }
      __syncthreads();
      float thr = z_sm[1] - WIN_BASE;
      unsigned base = (unsigned)(gw * 6 + j) * 50u;
      float z = __int_as_float(0xFF800000);
      if (tid < NMIX && y >= thr)
        z = __fadd_rn(y, gumbel_at(KMIX0, KMIX1, base + (unsigned)tid));
      z_sm[tid] = z;
      __syncthreads();
      if (tid == 0) {
        float best = __int_as_float(0xFF800000);
        int bi = 0;
        for (int c = 0; c < NMIX; ++c)
          if (z_sm[c] > best) { best = z_sm[c]; bi = c; }
        const float* p = g_full + (size_t)gw * NPAD + 4 + 150 * j;
        float mean = p[50 + bi];
        float lstd = p[100 + bi];
        float nrm = normal_at(KG0, KG1, (unsigned)(gw * 6 + j));
        float noise = __fmul_rn(nrm, 0.01f);
        out[(size_t)gw * 10 + 4 + j] = __fadd_rn(mean, __fmul_rn(expf(lstd), noise));
      }
    }
    __syncthreads();
  }
}

// ---------------- Launch ----------------
extern "C" void kernel_launch(void* const* d_in, const int* in_sizes, int n_in,
                              void* d_out, int out_size) {
  const float* A = (const float*)d_in[0];
  const float* W = (const float*)d_in[1];
  const float* bias = (const float*)d_in[2];
  float* out = (float*)d_out;

  const int ms_smem = BUF_ELEMS * 2 * 2;  // two buffers, 110592 B
  static bool attr_set = false;
  if (!attr_set) {
    cudaFuncSetAttribute(gemm_full_kernel,
                         cudaFuncAttributeMaxDynamicSharedMemorySize, ms_smem);
    attr_set = true;
  }

  zero_cnt_kernel<<<1, 1>>>();
  split_a_kernel<<<(int)((size_t)SB * H_DIM / 4 / 256), 256>>>(A);
  split_w_kernel<<<(int)((size_t)NPAD * H_DIM / 4 / 256), 256>>>(W);

  dim3 gfull(NPAD / 64, SB / 128);  // (15, 816)
  gemm_full_kernel<<<gfull, 256, ms_smem>>>(bias);

  sample_kernel<<<SB / 8, 256>>>(out);
  fixup_kernel<<<1024, 64>>>(A, W, bias, out);
}

// round 15
// speedup vs baseline: 1.1227x; 1.1227x over previous
#include <cuda_runtime.h>
#include <cuda_bf16.h>
#include <math.h>
#include <stdint.h>

#define H_DIM 1024
#define SB 104448
#define OUT_CH 904
#define NMIX 50
#define NPAD 1024           // 904 channels padded to 1024 (8 x 128)
#define FULLMASK 0xFFFFFFFFu
#define MARGIN_THR 0.75f    // decision-safe margin (>= 2x worst-case y error)
#define WIN_BASE 20.45f     // exact gumbel-window (spread <= 20.412)
#define WIN_WIDE 21.25f     // widened window for approx candidate capture
#define FLAG_CAP (1 << 20)
typedef unsigned long long ull;

__device__ __forceinline__ float fadd_s(float a, float b) { return __fadd_rn(a, b); }

// ---------------- Threefry2x32 (JAX partitionable) ----------------
struct U2 { unsigned a, b; };
__host__ __device__ constexpr unsigned rotl32(unsigned x, int r) {
  return (x << r) | (x >> (32 - r));
}
__host__ __device__ constexpr U2 threefry2x32(unsigned k0, unsigned k1,
                                              unsigned c0, unsigned c1) {
  unsigned ks[3] = {k0, k1, k0 ^ k1 ^ 0x1BD11BDAu};
  unsigned x0 = c0 + k0, x1 = c1 + k1;
  const int rot[2][4] = {{13, 15, 26, 6}, {17, 29, 16, 24}};
#pragma unroll
  for (int g = 0; g < 5; ++g) {
    const int* r = rot[g & 1];
#pragma unroll
    for (int i = 0; i < 4; ++i) { x0 += x1; x1 = rotl32(x1, r[i]); x1 ^= x0; }
    x0 += ks[(g + 1) % 3];
    x1 += ks[(g + 2) % 3] + (unsigned)(g + 1);
  }
  return U2{x0, x1};
}
constexpr unsigned KCMD0 = threefry2x32(0u, 42u, 0u, 0u).a;
constexpr unsigned KCMD1 = threefry2x32(0u, 42u, 0u, 0u).b;
constexpr unsigned KMIX0 = threefry2x32(0u, 42u, 0u, 1u).a;
constexpr unsigned KMIX1 = threefry2x32(0u, 42u, 0u, 1u).b;
constexpr unsigned KG0   = threefry2x32(0u, 42u, 0u, 2u).a;
constexpr unsigned KG1   = threefry2x32(0u, 42u, 0u, 2u).b;

__device__ __forceinline__ float bits_to_f01(unsigned k0, unsigned k1, unsigned idx) {
  U2 o = threefry2x32(k0, k1, 0u, idx);
  return __uint_as_float((((o.a ^ o.b) >> 9) | 0x3f800000u)) - 1.0f;
}
__device__ __forceinline__ float gumbel_at(unsigned k0, unsigned k1, unsigned idx) {
  float u = fmaxf(bits_to_f01(k0, k1, idx), 1.17549435e-38f);
  return -logf(-logf(u));
}
__device__ __forceinline__ float normal_at(unsigned k0, unsigned k1, unsigned idx) {
  const float lo = __int_as_float(0xBF7FFFFF);  // nextafterf(-1,0)
  float u = fmaxf(__fadd_rn(__fmul_rn(bits_to_f01(k0, k1, idx), 2.0f), lo), lo);
  return __fmul_rn(1.41421356237f, erfinvf(u));
}

// ---------------- Device scratch ----------------
__device__ float g_full[(size_t)SB * NPAD];
__device__ __nv_bfloat16 g_ah[(size_t)SB * H_DIM];
__device__ __nv_bfloat16 g_al[(size_t)SB * H_DIM];
__device__ __nv_bfloat16 g_wh[(size_t)NPAD * H_DIM];
__device__ __nv_bfloat16 g_wl[(size_t)NPAD * H_DIM];
__device__ int g_cnt;
__device__ int g_list[FLAG_CAP];

__global__ void zero_cnt_kernel() { g_cnt = 0; }

// ---------------- Splitters ----------------
__global__ void __launch_bounds__(256) split_a_kernel(const float* __restrict__ A) {
  size_t i = (size_t)blockIdx.x * 256 + threadIdx.x;
  float4 v = reinterpret_cast<const float4*>(A)[i];
  float f[4] = {v.x, v.y, v.z, v.w};
  ull hp = 0, lp = 0;
#pragma unroll
  for (int j = 0; j < 4; ++j) {
    __nv_bfloat16 h = __float2bfloat16(f[j]);
    __nv_bfloat16 l = __float2bfloat16(__fadd_rn(f[j], -__bfloat162float(h)));
    hp |= (ull)__bfloat16_as_ushort(h) << (16 * j);
    lp |= (ull)__bfloat16_as_ushort(l) << (16 * j);
  }
  reinterpret_cast<ull*>(g_ah)[i] = hp;
  reinterpret_cast<ull*>(g_al)[i] = lp;
}

__global__ void __launch_bounds__(256) split_w_kernel(const float* __restrict__ W) {
  size_t i = (size_t)blockIdx.x * 256 + threadIdx.x;
  int n = (int)(i / (H_DIM / 4));
  int k4 = (int)(i % (H_DIM / 4));
  ull hp = 0, lp = 0;
  if (n < OUT_CH) {
    float4 v = reinterpret_cast<const float4*>(W + (size_t)n * H_DIM)[k4];
    float f[4] = {v.x, v.y, v.z, v.w};
#pragma unroll
    for (int j = 0; j < 4; ++j) {
      __nv_bfloat16 h = __float2bfloat16(f[j]);
      __nv_bfloat16 l = __float2bfloat16(__fadd_rn(f[j], -__bfloat162float(h)));
      hp |= (ull)__bfloat16_as_ushort(h) << (16 * j);
      lp |= (ull)__bfloat16_as_ushort(l) << (16 * j);
    }
  }
  reinterpret_cast<ull*>(g_wh)[i] = hp;
  reinterpret_cast<ull*>(g_wl)[i] = lp;
}

// ---------------- HMMA GEMM: block 128x128, warp tile 32x64 -------------------
// D = Ah*Wh + Ah*Wl + Al*Wh (+bias). LDG+STS staging (r13 style, L1-cached).
// Per-element accumulation order IDENTICAL to r13: chunks asc, ks asc, hh/hl/lh.
#define MS_STRIDE 72  // 64 + 8 pad; 144B rows -> conflict-free ldmatrix

__device__ __forceinline__ void mma_bf16(float c[4], uint32_t a0, uint32_t a1,
                                         uint32_t a2, uint32_t a3,
                                         uint32_t b0, uint32_t b1) {
  asm volatile(
      "mma.sync.aligned.m16n8k16.row.col.f32.bf16.bf16.f32 "
      "{%0,%1,%2,%3}, {%4,%5,%6,%7}, {%8,%9}, {%0,%1,%2,%3};"
      : "+f"(c[0]), "+f"(c[1]), "+f"(c[2]), "+f"(c[3])
      : "r"(a0), "r"(a1), "r"(a2), "r"(a3), "r"(b0), "r"(b1));
}

#define LDMX4(R0, R1, R2, R3, ADDR)                                            \
  asm volatile("ldmatrix.sync.aligned.m8n8.x4.shared.b16 {%0,%1,%2,%3}, [%4];" \
               : "=r"(R0), "=r"(R1), "=r"(R2), "=r"(R3) : "r"(ADDR))

__device__ __forceinline__ uint32_t smem_u32(const void* p) {
  uint32_t a;
  asm("{ .reg .u64 t; cvta.to.shared.u64 t, %1; cvt.u32.u64 %0, t; }" : "=r"(a) : "l"(p));
  return a;
}

__global__ void __launch_bounds__(256, 2) gemm_full_kernel(const float* __restrict__ bias) {
  extern __shared__ __nv_bfloat16 sm[];
  __nv_bfloat16* sAh = sm;
  __nv_bfloat16* sAl = sAh + 128 * MS_STRIDE;
  __nv_bfloat16* sWh = sAl + 128 * MS_STRIDE;
  __nv_bfloat16* sWl = sWh + 128 * MS_STRIDE;

  const int bn = blockIdx.x * 128;  // 8 (fastest -> A hot in L2)
  const int bm = blockIdx.y * 128;  // 816
  const int tid = (int)threadIdx.x;
  const int wid = tid >> 5, lane = tid & 31;
  const int wm = (wid >> 1) * 32;   // 4 m-warps
  const int wn = (wid & 1) * 64;    // 2 n-warps, 64 cols each
  const int g = lane >> 2, q = lane & 3;

  const int a_row = wm + (lane & 15);
  const int a_sel = (lane & 16) ? 8 : 0;
  const int b_row = wn + (lane & 7) + ((lane & 16) ? 8 : 0);
  const int b_sel = (lane & 8) ? 8 : 0;

  const uint32_t uAh = smem_u32(sAh), uAl = smem_u32(sAl);
  const uint32_t uWh = smem_u32(sWh), uWl = smem_u32(sWl);

  float c[2][8][4];
#pragma unroll
  for (int mt = 0; mt < 2; ++mt)
#pragma unroll
    for (int nt = 0; nt < 8; ++nt)
#pragma unroll
      for (int r = 0; r < 4; ++r) c[mt][nt][r] = 0.0f;

  // staging slots: every thread does one 64B half-row of each tile
  const int sr = tid >> 1, sh = (tid & 1) * 32;

  for (int ch = 0; ch < H_DIM / 64; ++ch) {
    const int k0 = ch * 64;
    {
      const uint4* pah = reinterpret_cast<const uint4*>(g_ah + (size_t)(bm + sr) * H_DIM + k0 + sh);
      const uint4* pal = reinterpret_cast<const uint4*>(g_al + (size_t)(bm + sr) * H_DIM + k0 + sh);
      const uint4* pwh = reinterpret_cast<const uint4*>(g_wh + (size_t)(bn + sr) * H_DIM + k0 + sh);
      const uint4* pwl = reinterpret_cast<const uint4*>(g_wl + (size_t)(bn + sr) * H_DIM + k0 + sh);
      uint4* dah = reinterpret_cast<uint4*>(sAh + sr * MS_STRIDE + sh);
      uint4* dal = reinterpret_cast<uint4*>(sAl + sr * MS_STRIDE + sh);
      uint4* dwh = reinterpret_cast<uint4*>(sWh + sr * MS_STRIDE + sh);
      uint4* dwl = reinterpret_cast<uint4*>(sWl + sr * MS_STRIDE + sh);
#pragma unroll
      for (int i = 0; i < 4; ++i) {
        dah[i] = pah[i]; dal[i] = pal[i];
        dwh[i] = pwh[i]; dwl[i] = pwl[i];
      }
    }
    __syncthreads();

#pragma unroll
    for (int ks = 0; ks < 4; ++ks) {
      const int ak = ks * 16 + a_sel;
      const int bk = ks * 16 + b_sel;
      uint32_t ah[2][4], al[2][4];

      uint32_t aoff0 = (uint32_t)(a_row * MS_STRIDE + ak) * 2;
      uint32_t aoff1 = aoff0 + 16 * MS_STRIDE * 2;
      LDMX4(ah[0][0], ah[0][1], ah[0][2], ah[0][3], uAh + aoff0);
      LDMX4(ah[1][0], ah[1][1], ah[1][2], ah[1][3], uAh + aoff1);
      LDMX4(al[0][0], al[0][1], al[0][2], al[0][3], uAl + aoff0);
      LDMX4(al[1][0], al[1][1], al[1][2], al[1][3], uAl + aoff1);

#pragma unroll
      for (int p = 0; p < 4; ++p) {  // nt pairs {2p, 2p+1}
        uint32_t bh2[4], bl2[4];
        uint32_t boff = (uint32_t)((b_row + p * 16) * MS_STRIDE + bk) * 2;
        LDMX4(bh2[0], bh2[1], bh2[2], bh2[3], uWh + boff);
        LDMX4(bl2[0], bl2[1], bl2[2], bl2[3], uWl + boff);
#pragma unroll
        for (int mt = 0; mt < 2; ++mt)
#pragma unroll
          for (int l = 0; l < 2; ++l) {
            int nt = 2 * p + l;
            mma_bf16(c[mt][nt], ah[mt][0], ah[mt][1], ah[mt][2], ah[mt][3],
                     bh2[2 * l], bh2[2 * l + 1]);
            mma_bf16(c[mt][nt], ah[mt][0], ah[mt][1], ah[mt][2], ah[mt][3],
                     bl2[2 * l], bl2[2 * l + 1]);
            mma_bf16(c[mt][nt], al[mt][0], al[mt][1], al[mt][2], al[mt][3],
                     bh2[2 * l], bh2[2 * l + 1]);
          }
      }
    }
    __syncthreads();
  }

  // epilogue: +bias, store (skip padded cols >= 904)
#pragma unroll
  for (int mt = 0; mt < 2; ++mt) {
#pragma unroll
    for (int nt = 0; nt < 8; ++nt) {
      int row = bm + wm + mt * 16 + g;
      int col = bn + wn + nt * 8 + q * 2;
      if (col < OUT_CH) {
        float b0 = __ldg(&bias[col]), b1 = __ldg(&bias[col + 1]);
        float2* p0 = reinterpret_cast<float2*>(g_full + (size_t)row * NPAD + col);
        float2* p1 = reinterpret_cast<float2*>(g_full + (size_t)(row + 8) * NPAD + col);
        *p0 = make_float2(fadd_s(c[mt][nt][0], b0), fadd_s(c[mt][nt][1], b1));
        *p1 = make_float2(fadd_s(c[mt][nt][2], b0), fadd_s(c[mt][nt][3], b1));
      }
    }
  }
}

// ---------------- Sampling with safe-margin flagging ----------------
__global__ void __launch_bounds__(256) sample_kernel(float* __restrict__ out) {
  int gw = (int)((blockIdx.x * blockDim.x + threadIdx.x) >> 5);
  int lane = (int)(threadIdx.x & 31);
  if (gw >= SB) return;
  const float* row = g_full + (size_t)gw * NPAD;

  // ---- command: top-2 of (x/tau + gumbel) ----
  float m1 = __int_as_float(0xFF800000), m2 = m1;
  int i1 = lane;
  if (lane < 4)
    m1 = __fadd_rn(__fdiv_rn(row[lane], 1e-4f),
                   gumbel_at(KCMD0, KCMD1, (unsigned)(gw * 4 + lane)));
#pragma unroll
  for (int off = 16; off > 0; off >>= 1) {
    float om1 = __shfl_xor_sync(FULLMASK, m1, off);
    int oi1 = __shfl_xor_sync(FULLMASK, i1, off);
    float om2 = __shfl_xor_sync(FULLMASK, m2, off);
    if (om1 > m1 || (om1 == m1 && oi1 < i1)) {
      m2 = fmaxf(m1, om2); m1 = om1; i1 = oi1;
    } else {
      m2 = fmaxf(m2, om1);
    }
  }
  if (lane < 4) out[(size_t)gw * 10 + lane] = (lane == i1) ? 1.0f : 0.0f;
  if (lane == 0 && (m1 - m2) < MARGIN_THR) {
    int pos = atomicAdd(&g_cnt, 1);
    if (pos < FLAG_CAP) g_list[pos] = gw * 8 + 7;
  }

  // ---- 6 mixture rows ----
  for (int j = 0; j < 6; ++j) {
    const float* p = row + 4 + j * 150;
    const int t1 = lane + 32;
    const bool has1 = (t1 < NMIX);
    float x0 = p[lane];
    float x1 = has1 ? p[t1] : __int_as_float(0xFF800000);

    float mx = fmaxf(x0, x1);
#pragma unroll
    for (int off = 16; off > 0; off >>= 1)
      mx = fmaxf(mx, __shfl_xor_sync(FULLMASK, mx, off));
    float s = expf(x0 - mx) + (has1 ? expf(x1 - mx) : 0.0f);
#pragma unroll
    for (int off = 16; off > 0; off >>= 1)
      s += __shfl_xor_sync(FULLMASK, s, off);
    float lse = logf(s) + mx;

    float y0 = __fdiv_rn(__fadd_rn(x0, -lse), 1e-4f);
    float y1 = has1 ? __fdiv_rn(__fadd_rn(x1, -lse), 1e-4f) : __int_as_float(0xFF800000);
    float ym = fmaxf(y0, y1);
#pragma unroll
    for (int off = 16; off > 0; off >>= 1)
      ym = fmaxf(ym, __shfl_xor_sync(FULLMASK, ym, off));

    float thr = ym - WIN_WIDE;
    bool c0 = y0 >= thr;
    bool c1 = has1 && (y1 >= thr);
    unsigned b0m = __ballot_sync(FULLMASK, c0);
    unsigned b1m = __ballot_sync(FULLMASK, c1);
    int mixidx;
    if (__popc(b0m) + __popc(b1m) == 1) {
      mixidx = b0m ? (__ffs(b0m) - 1) : (__ffs(b1m) + 31);
    } else {
      unsigned base = (unsigned)(gw * 6 + j) * 50u;
      float z0 = c0 ? __fadd_rn(y0, gumbel_at(KMIX0, KMIX1, base + (unsigned)lane))
                    : __int_as_float(0xFF800000);
      float z1 = c1 ? __fadd_rn(y1, gumbel_at(KMIX0, KMIX1, base + (unsigned)t1))
                    : __int_as_float(0xFF800000);
      float w1 = z0, w2 = z1;
      int wi = lane;
      if (z1 > z0) { w1 = z1; wi = t1; w2 = z0; }
#pragma unroll
      for (int off = 16; off > 0; off >>= 1) {
        float ow1 = __shfl_xor_sync(FULLMASK, w1, off);
        int owi = __shfl_xor_sync(FULLMASK, wi, off);
        float ow2 = __shfl_xor_sync(FULLMASK, w2, off);
        if (ow1 > w1 || (ow1 == w1 && owi < wi)) {
          w2 = fmaxf(w1, ow2); w1 = ow1; wi = owi;
        } else {
          w2 = fmaxf(w2, ow1);
        }
      }
      mixidx = wi;
      if (lane == 0 && (w1 - w2) < MARGIN_THR) {
        int pos = atomicAdd(&g_cnt, 1);
        if (pos < FLAG_CAP) g_list[pos] = gw * 8 + j;
      }
    }

    if (lane == 0) {
      float mean = p[50 + mixidx];
      float lstd = p[100 + mixidx];
      float nrm = normal_at(KG0, KG1, (unsigned)(gw * 6 + j));
      float noise = __fmul_rn(nrm, 0.01f);
      out[(size_t)gw * 10 + 4 + j] = __fadd_rn(mean, __fmul_rn(expf(lstd), noise));
    }
  }
}

// ---------------- Fixup: exact kc=320 recompute for flagged rows -------------
__global__ void __launch_bounds__(64) fixup_kernel(
    const float* __restrict__ A, const float* __restrict__ W,
    const float* __restrict__ bias, float* __restrict__ out) {
  __shared__ float a_sm[H_DIM];
  __shared__ float x_sm[64];
  __shared__ float z_sm[64];

  int cnt = g_cnt;
  if (cnt > FLAG_CAP) cnt = FLAG_CAP;
  const int tid = (int)threadIdx.x;

  for (int it = (int)blockIdx.x; it < cnt; it += (int)gridDim.x) {
    int code = g_list[it];
    int gw = code >> 3, j = code & 7;

    for (int k = tid; k < H_DIM; k += 64) a_sm[k] = A[(size_t)gw * H_DIM + k];
    __syncthreads();

    int nch = (j == 7) ? 4 : NMIX;
    int ch0 = (j == 7) ? 0 : 4 + 150 * j;

    float x = __int_as_float(0xFF800000);
    if (tid < nch) {
      const float* wr = W + (size_t)(ch0 + tid) * H_DIM;
      float acc = 0.0f, tot = 0.0f;
      int k = 0;
#pragma unroll 1
      for (int seg = 0; seg < 4; ++seg) {
        int ke = (seg < 3) ? (seg + 1) * 320 : H_DIM;
#pragma unroll 4
        for (; k < ke; ++k) acc = fmaf(a_sm[k], __ldg(&wr[k]), acc);
        tot = __fadd_rn(tot, acc);
        acc = 0.0f;
      }
      x = __fadd_rn(tot, __ldg(&bias[ch0 + tid]));
    }
    x_sm[tid] = x;
    __syncthreads();

    if (j == 7) {
      if (tid == 0) {
        float best = __int_as_float(0xFF800000);
        int bi = 0;
        for (int c = 0; c < 4; ++c) {
          float v = __fadd_rn(__fdiv_rn(x_sm[c], 1e-4f),
                              gumbel_at(KCMD0, KCMD1, (unsigned)(gw * 4 + c)));
          if (v > best) { best = v; bi = c; }
        }
        for (int c = 0; c < 4; ++c)
          out[(size_t)gw * 10 + c] = (c == bi) ? 1.0f : 0.0f;
      }
    } else {
      if (tid == 0) {
        float mx = x_sm[0];
        for (int c = 1; c < NMIX; ++c) mx = fmaxf(mx, x_sm[c]);
        float s = 0.0f;
        for (int c = 0; c < NMIX; ++c) s = __fadd_rn(s, expf(x_sm[c] - mx));
        z_sm[0] = logf(s) + mx;
      }
      __syncthreads();
      float lse = z_sm[0];
      __syncthreads();
      float y = (tid < NMIX) ? __fdiv_rn(__fadd_rn(x_sm[tid], -lse), 1e-4f)
                             : __int_as_float(0xFF800000);
      x_sm[tid] = y;
      __syncthreads();
      if (tid == 0) {
        float ym = x_sm[0];
        for (int c = 1; c < NMIX; ++c) ym = fmaxf(ym, x_sm[c]);
        z_sm[1] = ym;
      }
      __syncthreads();
      float thr = z_sm[1] - WIN_BASE;
      unsigned base = (unsigned)(gw * 6 + j) * 50u;
      float z = __int_as_float(0xFF800000);
      if (tid < NMIX && y >= thr)
        z = __fadd_rn(y, gumbel_at(KMIX0, KMIX1, base + (unsigned)tid));
      z_sm[tid] = z;
      __syncthreads();
      if (tid == 0) {
        float best = __int_as_float(0xFF800000);
        int bi = 0;
        for (int c = 0; c < NMIX; ++c)
          if (z_sm[c] > best) { best = z_sm[c]; bi = c; }
        const float* p = g_full + (size_t)gw * NPAD + 4 + 150 * j;
        float mean = p[50 + bi];
        float lstd = p[100 + bi];
        float nrm = normal_at(KG0, KG1, (unsigned)(gw * 6 + j));
        float noise = __fmul_rn(nrm, 0.01f);
        out[(size_t)gw * 10 + 4 + j] = __fadd_rn(mean, __fmul_rn(expf(lstd), noise));
      }
    }
    __syncthreads();
  }
}

// ---------------- Launch ----------------
extern "C" void kernel_launch(void* const* d_in, const int* in_sizes, int n_in,
                              void* d_out, int out_size) {
  const float* A = (const float*)d_in[0];
  const float* W = (const float*)d_in[1];
  const float* bias = (const float*)d_in[2];
  float* out = (float*)d_out;

  const int ms_smem = 512 * MS_STRIDE * 2;  // 73728 B (single buffer)
  static bool attr_set = false;
  if (!attr_set) {
    cudaFuncSetAttribute(gemm_full_kernel,
                         cudaFuncAttributeMaxDynamicSharedMemorySize, ms_smem);
    attr_set = true;
  }

  zero_cnt_kernel<<<1, 1>>>();
  split_a_kernel<<<(int)((size_t)SB * H_DIM / 4 / 256), 256>>>(A);
  split_w_kernel<<<(int)((size_t)NPAD * H_DIM / 4 / 256), 256>>>(W);

  dim3 gfull(NPAD / 128, SB / 128);  // (8, 816)
  gemm_full_kernel<<<gfull, 256, ms_smem>>>(bias);

  sample_kernel<<<SB / 8, 256>>>(out);
  fixup_kernel<<<1024, 64>>>(A, W, bias, out);
}

// round 16
// speedup vs baseline: 1.2756x; 1.1362x over previous
#include <cuda_runtime.h>
#include <cuda_fp16.h>
#include <math.h>
#include <stdint.h>

#define H_DIM 1024
#define SB 104448
#define OUT_CH 904
#define NMIX 50
#define NPAD 1024           // 904 channels padded to 1024 (8 x 128)
#define FULLMASK 0xFFFFFFFFu
#define MARGIN_THR 20.0f    // 7-sigma of fp16-2term y-margin error (sigma~2.8)
#define WIN_BASE 20.45f     // exact gumbel-window (spread <= 20.412)
#define WIN_WIDE 50.0f      // 20.45 + 2 * (7-sigma y error ~14)
#define FLAG_CAP (1 << 20)
typedef unsigned long long ull;

__device__ __forceinline__ float fadd_s(float a, float b) { return __fadd_rn(a, b); }

// ---------------- Threefry2x32 (JAX partitionable) ----------------
struct U2 { unsigned a, b; };
__host__ __device__ constexpr unsigned rotl32(unsigned x, int r) {
  return (x << r) | (x >> (32 - r));
}
__host__ __device__ constexpr U2 threefry2x32(unsigned k0, unsigned k1,
                                              unsigned c0, unsigned c1) {
  unsigned ks[3] = {k0, k1, k0 ^ k1 ^ 0x1BD11BDAu};
  unsigned x0 = c0 + k0, x1 = c1 + k1;
  const int rot[2][4] = {{13, 15, 26, 6}, {17, 29, 16, 24}};
#pragma unroll
  for (int g = 0; g < 5; ++g) {
    const int* r = rot[g & 1];
#pragma unroll
    for (int i = 0; i < 4; ++i) { x0 += x1; x1 = rotl32(x1, r[i]); x1 ^= x0; }
    x0 += ks[(g + 1) % 3];
    x1 += ks[(g + 2) % 3] + (unsigned)(g + 1);
  }
  return U2{x0, x1};
}
constexpr unsigned KCMD0 = threefry2x32(0u, 42u, 0u, 0u).a;
constexpr unsigned KCMD1 = threefry2x32(0u, 42u, 0u, 0u).b;
constexpr unsigned KMIX0 = threefry2x32(0u, 42u, 0u, 1u).a;
constexpr unsigned KMIX1 = threefry2x32(0u, 42u, 0u, 1u).b;
constexpr unsigned KG0   = threefry2x32(0u, 42u, 0u, 2u).a;
constexpr unsigned KG1   = threefry2x32(0u, 42u, 0u, 2u).b;

__device__ __forceinline__ float bits_to_f01(unsigned k0, unsigned k1, unsigned idx) {
  U2 o = threefry2x32(k0, k1, 0u, idx);
  return __uint_as_float((((o.a ^ o.b) >> 9) | 0x3f800000u)) - 1.0f;
}
__device__ __forceinline__ float gumbel_at(unsigned k0, unsigned k1, unsigned idx) {
  float u = fmaxf(bits_to_f01(k0, k1, idx), 1.17549435e-38f);
  return -logf(-logf(u));
}
__device__ __forceinline__ float normal_at(unsigned k0, unsigned k1, unsigned idx) {
  const float lo = __int_as_float(0xBF7FFFFF);  // nextafterf(-1,0)
  float u = fmaxf(__fadd_rn(__fmul_rn(bits_to_f01(k0, k1, idx), 2.0f), lo), lo);
  return __fmul_rn(1.41421356237f, erfinvf(u));
}

// ---------------- Device scratch ----------------
__device__ float g_full[(size_t)SB * NPAD];
__device__ __half g_ah[(size_t)SB * H_DIM];     // A in fp16 (hi only)
__device__ __half g_wh[(size_t)NPAD * H_DIM];   // W hi
__device__ __half g_wl[(size_t)NPAD * H_DIM];   // W residual
__device__ int g_cnt;
__device__ int g_list[FLAG_CAP];

__global__ void zero_cnt_kernel() { g_cnt = 0; }

// ---------------- Splitters ----------------
__global__ void __launch_bounds__(256) split_a_kernel(const float* __restrict__ A) {
  size_t i = (size_t)blockIdx.x * 256 + threadIdx.x;  // one float4 per thread
  float4 v = reinterpret_cast<const float4*>(A)[i];
  float f[4] = {v.x, v.y, v.z, v.w};
  ull hp = 0;
#pragma unroll
  for (int j = 0; j < 4; ++j) {
    __half h = __float2half_rn(f[j]);
    hp |= (ull)__half_as_ushort(h) << (16 * j);
  }
  reinterpret_cast<ull*>(g_ah)[i] = hp;
}

__global__ void __launch_bounds__(256) split_w_kernel(const float* __restrict__ W) {
  size_t i = (size_t)blockIdx.x * 256 + threadIdx.x;
  int n = (int)(i / (H_DIM / 4));
  int k4 = (int)(i % (H_DIM / 4));
  ull hp = 0, lp = 0;
  if (n < OUT_CH) {
    float4 v = reinterpret_cast<const float4*>(W + (size_t)n * H_DIM)[k4];
    float f[4] = {v.x, v.y, v.z, v.w};
#pragma unroll
    for (int j = 0; j < 4; ++j) {
      __half h = __float2half_rn(f[j]);
      __half l = __float2half_rn(__fadd_rn(f[j], -__half2float(h)));
      hp |= (ull)__half_as_ushort(h) << (16 * j);
      lp |= (ull)__half_as_ushort(l) << (16 * j);
    }
  }
  reinterpret_cast<ull*>(g_wh)[i] = hp;
  reinterpret_cast<ull*>(g_wl)[i] = lp;
}

// ---------------- HMMA GEMM fp16 2-term: block 128x128, warp 32x64 -----------
// D = Ah*Wh + Ah*Wl (+bias). Per element: ks ascending, hh then hl.
#define MS_STRIDE 72  // 64 + 8 pad; 144B rows -> conflict-free ldmatrix

__device__ __forceinline__ void mma_f16(float c[4], uint32_t a0, uint32_t a1,
                                        uint32_t a2, uint32_t a3,
                                        uint32_t b0, uint32_t b1) {
  asm volatile(
      "mma.sync.aligned.m16n8k16.row.col.f32.f16.f16.f32 "
      "{%0,%1,%2,%3}, {%4,%5,%6,%7}, {%8,%9}, {%0,%1,%2,%3};"
      : "+f"(c[0]), "+f"(c[1]), "+f"(c[2]), "+f"(c[3])
      : "r"(a0), "r"(a1), "r"(a2), "r"(a3), "r"(b0), "r"(b1));
}

#define LDMX4(R0, R1, R2, R3, ADDR)                                            \
  asm volatile("ldmatrix.sync.aligned.m8n8.x4.shared.b16 {%0,%1,%2,%3}, [%4];" \
               : "=r"(R0), "=r"(R1), "=r"(R2), "=r"(R3) : "r"(ADDR))

__device__ __forceinline__ uint32_t smem_u32(const void* p) {
  uint32_t a;
  asm("{ .reg .u64 t; cvta.to.shared.u64 t, %1; cvt.u32.u64 %0, t; }" : "=r"(a) : "l"(p));
  return a;
}

__global__ void __launch_bounds__(256, 2) gemm_full_kernel(const float* __restrict__ bias) {
  extern __shared__ __half sm[];
  __half* sAh = sm;
  __half* sWh = sAh + 128 * MS_STRIDE;
  __half* sWl = sWh + 128 * MS_STRIDE;

  const int bn = blockIdx.x * 128;  // 8 (fastest -> A hot in L2)
  const int bm = blockIdx.y * 128;  // 816
  const int tid = (int)threadIdx.x;
  const int wid = tid >> 5, lane = tid & 31;
  const int wm = (wid >> 1) * 32;   // 4 m-warps
  const int wn = (wid & 1) * 64;    // 2 n-warps, 64 cols each
  const int g = lane >> 2, q = lane & 3;

  const int a_row = wm + (lane & 15);
  const int a_sel = (lane & 16) ? 8 : 0;
  const int b_row = wn + (lane & 7) + ((lane & 16) ? 8 : 0);
  const int b_sel = (lane & 8) ? 8 : 0;

  const uint32_t uAh = smem_u32(sAh);
  const uint32_t uWh = smem_u32(sWh), uWl = smem_u32(sWl);

  float c[2][8][4];
#pragma unroll
  for (int mt = 0; mt < 2; ++mt)
#pragma unroll
    for (int nt = 0; nt < 8; ++nt)
#pragma unroll
      for (int r = 0; r < 4; ++r) c[mt][nt][r] = 0.0f;

  const int sr = tid >> 1, sh = (tid & 1) * 32;

  for (int ch = 0; ch < H_DIM / 64; ++ch) {
    const int k0 = ch * 64;
    {
      const uint4* pah = reinterpret_cast<const uint4*>(g_ah + (size_t)(bm + sr) * H_DIM + k0 + sh);
      const uint4* pwh = reinterpret_cast<const uint4*>(g_wh + (size_t)(bn + sr) * H_DIM + k0 + sh);
      const uint4* pwl = reinterpret_cast<const uint4*>(g_wl + (size_t)(bn + sr) * H_DIM + k0 + sh);
      uint4* dah = reinterpret_cast<uint4*>(sAh + sr * MS_STRIDE + sh);
      uint4* dwh = reinterpret_cast<uint4*>(sWh + sr * MS_STRIDE + sh);
      uint4* dwl = reinterpret_cast<uint4*>(sWl + sr * MS_STRIDE + sh);
#pragma unroll
      for (int i = 0; i < 4; ++i) { dah[i] = pah[i]; dwh[i] = pwh[i]; dwl[i] = pwl[i]; }
    }
    __syncthreads();

#pragma unroll
    for (int ks = 0; ks < 4; ++ks) {
      const int ak = ks * 16 + a_sel;
      const int bk = ks * 16 + b_sel;
      uint32_t ah[2][4];

      uint32_t aoff0 = (uint32_t)(a_row * MS_STRIDE + ak) * 2;
      uint32_t aoff1 = aoff0 + 16 * MS_STRIDE * 2;
      LDMX4(ah[0][0], ah[0][1], ah[0][2], ah[0][3], uAh + aoff0);
      LDMX4(ah[1][0], ah[1][1], ah[1][2], ah[1][3], uAh + aoff1);

#pragma unroll
      for (int p = 0; p < 4; ++p) {  // nt pairs {2p, 2p+1}
        uint32_t bh2[4], bl2[4];
        uint32_t boff = (uint32_t)((b_row + p * 16) * MS_STRIDE + bk) * 2;
        LDMX4(bh2[0], bh2[1], bh2[2], bh2[3], uWh + boff);
        LDMX4(bl2[0], bl2[1], bl2[2], bl2[3], uWl + boff);
#pragma unroll
        for (int mt = 0; mt < 2; ++mt)
#pragma unroll
          for (int l = 0; l < 2; ++l) {
            int nt = 2 * p + l;
            mma_f16(c[mt][nt], ah[mt][0], ah[mt][1], ah[mt][2], ah[mt][3],
                    bh2[2 * l], bh2[2 * l + 1]);
            mma_f16(c[mt][nt], ah[mt][0], ah[mt][1], ah[mt][2], ah[mt][3],
                    bl2[2 * l], bl2[2 * l + 1]);
          }
      }
    }
    __syncthreads();
  }

  // epilogue: +bias, store (skip padded cols >= 904)
#pragma unroll
  for (int mt = 0; mt < 2; ++mt) {
#pragma unroll
    for (int nt = 0; nt < 8; ++nt) {
      int row = bm + wm + mt * 16 + g;
      int col = bn + wn + nt * 8 + q * 2;
      if (col < OUT_CH) {
        float b0 = __ldg(&bias[col]), b1 = __ldg(&bias[col + 1]);
        float2* p0 = reinterpret_cast<float2*>(g_full + (size_t)row * NPAD + col);
        float2* p1 = reinterpret_cast<float2*>(g_full + (size_t)(row + 8) * NPAD + col);
        *p0 = make_float2(fadd_s(c[mt][nt][0], b0), fadd_s(c[mt][nt][1], b1));
        *p1 = make_float2(fadd_s(c[mt][nt][2], b0), fadd_s(c[mt][nt][3], b1));
      }
    }
  }
}

// ---------------- Sampling with safe-margin flagging ----------------
__global__ void __launch_bounds__(256) sample_kernel(float* __restrict__ out) {
  int gw = (int)((blockIdx.x * blockDim.x + threadIdx.x) >> 5);
  int lane = (int)(threadIdx.x & 31);
  if (gw >= SB) return;
  const float* row = g_full + (size_t)gw * NPAD;

  // ---- command: top-2 of (x/tau + gumbel) ----
  float m1 = __int_as_float(0xFF800000), m2 = m1;
  int i1 = lane;
  if (lane < 4)
    m1 = __fadd_rn(__fdiv_rn(row[lane], 1e-4f),
                   gumbel_at(KCMD0, KCMD1, (unsigned)(gw * 4 + lane)));
#pragma unroll
  for (int off = 16; off > 0; off >>= 1) {
    float om1 = __shfl_xor_sync(FULLMASK, m1, off);
    int oi1 = __shfl_xor_sync(FULLMASK, i1, off);
    float om2 = __shfl_xor_sync(FULLMASK, m2, off);
    if (om1 > m1 || (om1 == m1 && oi1 < i1)) {
      m2 = fmaxf(m1, om2); m1 = om1; i1 = oi1;
    } else {
      m2 = fmaxf(m2, om1);
    }
  }
  if (lane < 4) out[(size_t)gw * 10 + lane] = (lane == i1) ? 1.0f : 0.0f;
  if (lane == 0 && (m1 - m2) < MARGIN_THR) {
    int pos = atomicAdd(&g_cnt, 1);
    if (pos < FLAG_CAP) g_list[pos] = gw * 8 + 7;
  }

  // ---- 6 mixture rows ----
  for (int j = 0; j < 6; ++j) {
    const float* p = row + 4 + j * 150;
    const int t1 = lane + 32;
    const bool has1 = (t1 < NMIX);
    float x0 = p[lane];
    float x1 = has1 ? p[t1] : __int_as_float(0xFF800000);

    float mx = fmaxf(x0, x1);
#pragma unroll
    for (int off = 16; off > 0; off >>= 1)
      mx = fmaxf(mx, __shfl_xor_sync(FULLMASK, mx, off));
    float s = expf(x0 - mx) + (has1 ? expf(x1 - mx) : 0.0f);
#pragma unroll
    for (int off = 16; off > 0; off >>= 1)
      s += __shfl_xor_sync(FULLMASK, s, off);
    float lse = logf(s) + mx;

    float y0 = __fdiv_rn(__fadd_rn(x0, -lse), 1e-4f);
    float y1 = has1 ? __fdiv_rn(__fadd_rn(x1, -lse), 1e-4f) : __int_as_float(0xFF800000);
    float ym = fmaxf(y0, y1);
#pragma unroll
    for (int off = 16; off > 0; off >>= 1)
      ym = fmaxf(ym, __shfl_xor_sync(FULLMASK, ym, off));

    float thr = ym - WIN_WIDE;
    bool c0 = y0 >= thr;
    bool c1 = has1 && (y1 >= thr);
    unsigned b0m = __ballot_sync(FULLMASK, c0);
    unsigned b1m = __ballot_sync(FULLMASK, c1);
    int mixidx;
    if (__popc(b0m) + __popc(b1m) == 1) {
      mixidx = b0m ? (__ffs(b0m) - 1) : (__ffs(b1m) + 31);
    } else {
      unsigned base = (unsigned)(gw * 6 + j) * 50u;
      float z0 = c0 ? __fadd_rn(y0, gumbel_at(KMIX0, KMIX1, base + (unsigned)lane))
                    : __int_as_float(0xFF800000);
      float z1 = c1 ? __fadd_rn(y1, gumbel_at(KMIX0, KMIX1, base + (unsigned)t1))
                    : __int_as_float(0xFF800000);
      float w1 = z0, w2 = z1;
      int wi = lane;
      if (z1 > z0) { w1 = z1; wi = t1; w2 = z0; }
#pragma unroll
      for (int off = 16; off > 0; off >>= 1) {
        float ow1 = __shfl_xor_sync(FULLMASK, w1, off);
        int owi = __shfl_xor_sync(FULLMASK, wi, off);
        float ow2 = __shfl_xor_sync(FULLMASK, w2, off);
        if (ow1 > w1 || (ow1 == w1 && owi < wi)) {
          w2 = fmaxf(w1, ow2); w1 = ow1; wi = owi;
        } else {
          w2 = fmaxf(w2, ow1);
        }
      }
      mixidx = wi;
      if (lane == 0 && (w1 - w2) < MARGIN_THR) {
        int pos = atomicAdd(&g_cnt, 1);
        if (pos < FLAG_CAP) g_list[pos] = gw * 8 + j;
      }
    }

    if (lane == 0) {
      float mean = p[50 + mixidx];
      float lstd = p[100 + mixidx];
      float nrm = normal_at(KG0, KG1, (unsigned)(gw * 6 + j));
      float noise = __fmul_rn(nrm, 0.01f);
      out[(size_t)gw * 10 + 4 + j] = __fadd_rn(mean, __fmul_rn(expf(lstd), noise));
    }
  }
}

// ---------------- Fixup: exact kc=320 recompute for flagged rows -------------
__global__ void __launch_bounds__(64) fixup_kernel(
    const float* __restrict__ A, const float* __restrict__ W,
    const float* __restrict__ bias, float* __restrict__ out) {
  __shared__ float a_sm[H_DIM];
  __shared__ float x_sm[64];
  __shared__ float z_sm[64];

  int cnt = g_cnt;
  if (cnt > FLAG_CAP) cnt = FLAG_CAP;
  const int tid = (int)threadIdx.x;

  for (int it = (int)blockIdx.x; it < cnt; it += (int)gridDim.x) {
    int code = g_list[it];
    int gw = code >> 3, j = code & 7;

    for (int k = tid; k < H_DIM; k += 64) a_sm[k] = A[(size_t)gw * H_DIM + k];
    __syncthreads();

    int nch = (j == 7) ? 4 : NMIX;
    int ch0 = (j == 7) ? 0 : 4 + 150 * j;

    float x = __int_as_float(0xFF800000);
    if (tid < nch) {
      const float* wr = W + (size_t)(ch0 + tid) * H_DIM;
      float acc = 0.0f, tot = 0.0f;
      int k = 0;
#pragma unroll 1
      for (int seg = 0; seg < 4; ++seg) {
        int ke = (seg < 3) ? (seg + 1) * 320 : H_DIM;
#pragma unroll 4
        for (; k < ke; ++k) acc = fmaf(a_sm[k], __ldg(&wr[k]), acc);
        tot = __fadd_rn(tot, acc);
        acc = 0.0f;
      }
      x = __fadd_rn(tot, __ldg(&bias[ch0 + tid]));
    }
    x_sm[tid] = x;
    __syncthreads();

    if (j == 7) {
      if (tid == 0) {
        float best = __int_as_float(0xFF800000);
        int bi = 0;
        for (int c = 0; c < 4; ++c) {
          float v = __fadd_rn(__fdiv_rn(x_sm[c], 1e-4f),
                              gumbel_at(KCMD0, KCMD1, (unsigned)(gw * 4 + c)));
          if (v > best) { best = v; bi = c; }
        }
        for (int c = 0; c < 4; ++c)
          out[(size_t)gw * 10 + c] = (c == bi) ? 1.0f : 0.0f;
      }
    } else {
      if (tid == 0) {
        float mx = x_sm[0];
        for (int c = 1; c < NMIX; ++c) mx = fmaxf(mx, x_sm[c]);
        float s = 0.0f;
        for (int c = 0; c < NMIX; ++c) s = __fadd_rn(s, expf(x_sm[c] - mx));
        z_sm[0] = logf(s) + mx;
      }
      __syncthreads();
      float lse = z_sm[0];
      __syncthreads();
      float y = (tid < NMIX) ? __fdiv_rn(__fadd_rn(x_sm[tid], -lse), 1e-4f)
                             : __int_as_float(0xFF800000);
      x_sm[tid] = y;
      __syncthreads();
      if (tid == 0) {
        float ym = x_sm[0];
        for (int c = 1; c < NMIX; ++c) ym = fmaxf(ym, x_sm[c]);
        z_sm[1] = ym;
      }
      __syncthreads();
      float thr = z_sm[1] - WIN_BASE;
      unsigned base = (unsigned)(gw * 6 + j) * 50u;
      float z = __int_as_float(0xFF800000);
      if (tid < NMIX && y >= thr)
        z = __fadd_rn(y, gumbel_at(KMIX0, KMIX1, base + (unsigned)tid));
      z_sm[tid] = z;
      __syncthreads();
      if (tid == 0) {
        float best = __int_as_float(0xFF800000);
        int bi = 0;
        for (int c = 0; c < NMIX; ++c)
          if (z_sm[c] > best) { best = z_sm[c]; bi = c; }
        const float* p = g_full + (size_t)gw * NPAD + 4 + 150 * j;
        float mean = p[50 + bi];
        float lstd = p[100 + bi];
        float nrm = normal_at(KG0, KG1, (unsigned)(gw * 6 + j));
        float noise = __fmul_rn(nrm, 0.01f);
        out[(size_t)gw * 10 + 4 + j] = __fadd_rn(mean, __fmul_rn(expf(lstd), noise));
      }
    }
    __syncthreads();
  }
}

// ---------------- Launch ----------------
extern "C" void kernel_launch(void* const* d_in, const int* in_sizes, int n_in,
                              void* d_out, int out_size) {
  const float* A = (const float*)d_in[0];
  const float* W = (const float*)d_in[1];
  const float* bias = (const float*)d_in[2];
  float* out = (float*)d_out;

  const int ms_smem = 384 * MS_STRIDE * 2;  // 55296 B (3 tiles)
  static bool attr_set = false;
  if (!attr_set) {
    cudaFuncSetAttribute(gemm_full_kernel,
                         cudaFuncAttributeMaxDynamicSharedMemorySize, ms_smem);
    attr_set = true;
  }

  zero_cnt_kernel<<<1, 1>>>();
  split_a_kernel<<<(int)((size_t)SB * H_DIM / 4 / 256), 256>>>(A);
  split_w_kernel<<<(int)((size_t)NPAD * H_DIM / 4 / 256), 256>>>(W);

  dim3 gfull(NPAD / 128, SB / 128);  // (8, 816)
  gemm_full_kernel<<<gfull, 256, ms_smem>>>(bias);

  sample_kernel<<<SB / 8, 256>>>(out);
  fixup_kernel<<<1024, 64>>>(A, W, bias, out);
}